// round 15
// baseline (speedup 1.0000x reference)
#include <cuda_runtime.h>

// Problem constants
static constexpr int N_MC = 32;
static constexpr int M    = 8192;
static constexpr int D    = 16;

#define TWOPI_F   6.2831853071795864769f   // rounds to float32(2*pi)
#define NEG_HALF_LOG_2PI -0.9189385332046727f
#define LN2_F     0.69314718055994530942f
#define LOG2E_F   1.4426950408889634074f
#define K_W      (-28.476200801864298f)    // -4*pi^2*log2(e)/2: warg = K_W*in^2

typedef unsigned long long u64;

// Packed f32x2 broadcast constants (same f32 bits in both lanes)
#define MG2     0x4B4000004B400000ull   // ( 1.5*2^23,  1.5*2^23)
#define NMG2    0xCB400000CB400000ull   // (-1.5*2^23, -1.5*2^23)
#define INV2PI2 0x3E22F9833E22F983ull   // (1/2pi, 1/2pi)
#define NTWOPI2 0xC0C90FDBC0C90FDBull   // (-2pi, -2pi)
#define ONE2    0x3F8000003F800000ull   // (1, 1)

__device__ __forceinline__ float ex2f(float x) {
    float y; asm("ex2.approx.f32 %0, %1;" : "=f"(y) : "f"(x)); return y;
}
__device__ __forceinline__ float lg2f(float x) {
    float y; asm("lg2.approx.f32 %0, %1;" : "=f"(y) : "f"(x)); return y;
}
__device__ __forceinline__ float rcpf(float x) {
    float y; asm("rcp.approx.f32 %0, %1;" : "=f"(y) : "f"(x)); return y;
}
__device__ __forceinline__ u64 pk(float lo, float hi) {
    u64 r; asm("mov.b64 %0, {%1, %2};" : "=l"(r) : "f"(lo), "f"(hi)); return r;
}
__device__ __forceinline__ void upk(float& lo, float& hi, u64 v) {
    asm("mov.b64 {%0, %1}, %2;" : "=f"(lo), "=f"(hi) : "l"(v));
}
__device__ __forceinline__ u64 fma2(u64 a, u64 b, u64 c) {
    u64 d; asm("fma.rn.f32x2 %0, %1, %2, %3;" : "=l"(d) : "l"(a), "l"(b), "l"(c)); return d;
}
__device__ __forceinline__ u64 add2(u64 a, u64 b) {
    u64 d; asm("add.rn.f32x2 %0, %1, %2;" : "=l"(d) : "l"(a), "l"(b)); return d;
}
__device__ __forceinline__ u64 mul2(u64 a, u64 b) {
    u64 d; asm("mul.rn.f32x2 %0, %1, %2;" : "=l"(d) : "l"(a), "l"(b)); return d;
}

struct Consts {
    u64 s01, s23, m01, m23, na01, na23, al01, al23, w01, w23;
};

// One dim-PAIR, fully packed f32x2.
//   g:  magic-rint + exact fma remainder + scalar fixup (bit-safe, R1-R13)
//   lq: u-direct form  u = eps - k*a ;  p = 1 + w*exp(a|u|)  (2-term lattice)
__device__ __forceinline__ void dimpair(
    u64 e2, u64 s2, u64 mu2, u64 na2, u64 al2, u64 w2,
    float& g_lo, float& g_hi, u64& uacc2, u64& P2)
{
    u64 x2 = mul2(e2, s2);
    // ---- g = mod(x+mu, 2pi) ----
    u64 v2 = add2(x2, mu2);
    u64 q2 = add2(fma2(v2, INV2PI2, MG2), NMG2);
    u64 t2 = fma2(q2, NTWOPI2, v2);
    float tl, th; upk(tl, th, t2);
    if (tl < 0.0f) tl += TWOPI_F;
    if (th < 0.0f) th += TWOPI_F;
    g_lo = tl; g_hi = th;
    // ---- lq ----
    u64 k2 = add2(fma2(x2, INV2PI2, MG2), NMG2);
    u64 u2 = fma2(k2, na2, e2);          // u = eps - k*a
    uacc2  = fma2(u2, u2, uacc2);
    float cl, ch; upk(cl, ch, mul2(u2, al2));   // c = u*a*log2e
    P2 = mul2(P2, fma2(w2, pk(ex2f(fabsf(cl)), ex2f(fabsf(ch))), ONE2));
}

__device__ __forceinline__ float elem(const float4 e, const Consts& C,
                                      float4* __restrict__ gptr)
{
    float4 g;
    u64 u2 = 0, P2 = ONE2;
    dimpair(pk(e.x, e.y), C.s01, C.m01, C.na01, C.al01, C.w01, g.x, g.y, u2, P2);
    dimpair(pk(e.z, e.w), C.s23, C.m23, C.na23, C.al23, C.w23, g.z, g.w, u2, P2);
    *gptr = g;
    float u0, u1, p0, p1;
    upk(u0, u1, u2); upk(p0, p1, P2);
    return fmaf(u0 + u1, -0.5f, LN2_F * lg2f(p0 * p1));
}

// Single fused kernel, warp-cooperative preamble.
// Warp w owns row m = w.  Lane = (q, dq): q = lane>>2 in 0..7 (n-group,
// n in [4q, 4q+4)), dq = lane&3 (dim quad).  The softplus preamble is
// computed once per TWO lanes (lane does dim d = lane&15) and the per-dim
// constants are distributed with shfl.idx (bit-preserving, so the bit-exact
// g path is unchanged).  8x preamble redundancy -> 2x.
__global__ void __launch_bounds__(256) relie_fused(
    const float4* __restrict__ eps4,    // 2^20 float4  (n, m, d)
    const float*  __restrict__ gam,     // M*D floats
    const float4* __restrict__ mu4,     // M*4 float4
    float4*       __restrict__ g4,      // 2^20 float4
    float*        __restrict__ lq)      // N*M floats
{
    int tid  = blockIdx.x * blockDim.x + threadIdx.x;   // 0 .. 2^18-1
    int m    = tid >> 5;                // warp id = row m
    int lane = tid & 31;
    int q    = lane >> 2;               // n-group
    int dq   = lane & 3;                // dim quad

    // ---- issue all global loads first (overlap DRAM wait with preamble) ----
    const int ROW = M * 4;              // float4 stride per MC sample
    int base = (q << 2) * ROW + (m << 2) + dq;
    float4 e0 = eps4[base          ];
    float4 e1 = eps4[base +     ROW];
    float4 e2 = eps4[base + 2 * ROW];
    float4 e3 = eps4[base + 3 * ROW];
    float4 mu = mu4[(m << 2) + dq];     // same addr for all 8 q-lanes: bcast
    float raw = gam[(m << 4) + (lane & 15)];   // this lane's preamble dim

    // ---- cooperative preamble: ONE softplus per lane ----
    // EXACT jax.nn.softplus: max(x,0)+log1p(exp(-|x|)), precise libdevice
    float s  = fmaxf(raw, 0.0f) + log1pf(expf(-fabsf(raw)));
    float in = rcpf(s);                 // approx ok: feeds lq only
    float a  = TWOPI_F * in;
    float na = -a;
    float al = a * LOG2E_F;
    float w  = ex2f(K_W * (in * in));   // exp(-a^2/2)
    float ln = NEG_HALF_LOG_2PI - LN2_F * lg2f(s);
    // C_m = sum over 16 dims (both 16-lane halves hold the same dims)
    ln += __shfl_xor_sync(0xffffffffu, ln, 1);
    ln += __shfl_xor_sync(0xffffffffu, ln, 2);
    ln += __shfl_xor_sync(0xffffffffu, ln, 4);
    ln += __shfl_xor_sync(0xffffffffu, ln, 8);
    float Cm = ln;

    // ---- distribute this lane's 4 dims (4dq..4dq+3) via shfl.idx ----
    int b0 = dq << 2;
    float s0  = __shfl_sync(0xffffffffu, s,  b0    );
    float s1  = __shfl_sync(0xffffffffu, s,  b0 + 1);
    float s2  = __shfl_sync(0xffffffffu, s,  b0 + 2);
    float s3  = __shfl_sync(0xffffffffu, s,  b0 + 3);
    float na0 = __shfl_sync(0xffffffffu, na, b0    );
    float na1 = __shfl_sync(0xffffffffu, na, b0 + 1);
    float na2 = __shfl_sync(0xffffffffu, na, b0 + 2);
    float na3 = __shfl_sync(0xffffffffu, na, b0 + 3);
    float al0 = __shfl_sync(0xffffffffu, al, b0    );
    float al1 = __shfl_sync(0xffffffffu, al, b0 + 1);
    float al2 = __shfl_sync(0xffffffffu, al, b0 + 2);
    float al3 = __shfl_sync(0xffffffffu, al, b0 + 3);
    float w0  = __shfl_sync(0xffffffffu, w,  b0    );
    float w1  = __shfl_sync(0xffffffffu, w,  b0 + 1);
    float w2  = __shfl_sync(0xffffffffu, w,  b0 + 2);
    float w3  = __shfl_sync(0xffffffffu, w,  b0 + 3);

    Consts C;
    C.s01  = pk(s0,  s1);  C.s23  = pk(s2,  s3);
    C.m01  = pk(mu.x, mu.y); C.m23 = pk(mu.z, mu.w);
    C.na01 = pk(na0, na1); C.na23 = pk(na2, na3);
    C.al01 = pk(al0, al1); C.al23 = pk(al2, al3);
    C.w01  = pk(w0,  w1);  C.w23  = pk(w2,  w3);

    float v0 = elem(e0, C, g4 + base          );
    float v1 = elem(e1, C, g4 + base +     ROW);
    float v2 = elem(e2, C, g4 + base + 2 * ROW);
    float v3 = elem(e3, C, g4 + base + 3 * ROW);

    // ---- lq reductions over the dq quad (lanes 4q..4q+3) ----
    v0 += __shfl_xor_sync(0xffffffffu, v0, 1);
    v0 += __shfl_xor_sync(0xffffffffu, v0, 2);
    v1 += __shfl_xor_sync(0xffffffffu, v1, 1);
    v1 += __shfl_xor_sync(0xffffffffu, v1, 2);
    v2 += __shfl_xor_sync(0xffffffffu, v2, 1);
    v2 += __shfl_xor_sync(0xffffffffu, v2, 2);
    v3 += __shfl_xor_sync(0xffffffffu, v3, 1);
    v3 += __shfl_xor_sync(0xffffffffu, v3, 2);
    if (dq == 0) {
        int nm = (q << 2) * M + m;      // n0 = 4q
        lq[nm        ] = v0 + Cm;
        lq[nm +     M] = v1 + Cm;
        lq[nm + 2 * M] = v2 + Cm;
        lq[nm + 3 * M] = v3 + Cm;
    }
}

extern "C" void kernel_launch(void* const* d_in, const int* in_sizes, int n_in,
                              void* d_out, int out_size) {
    const float* eps       = (const float*)d_in[0];  // (32, 8192, 16)
    const float* gamma_raw = (const float*)d_in[1];  // (8192, 16)
    const float* mu        = (const float*)d_in[2];  // (8192, 16)

    float* g_out  = (float*)d_out;                          // N*M*D floats
    float* lq_out = (float*)d_out + (size_t)N_MC * M * D;   // N*M floats

    relie_fused<<<(1 << 18) / 256, 256>>>(
        (const float4*)eps, gamma_raw, (const float4*)mu,
        (float4*)g_out, lq_out);
}